// round 9
// baseline (speedup 1.0000x reference)
#include <cuda_runtime.h>
#include <cuda_fp16.h>
#include <math.h>

// Problem constants
#define B_      256
#define U_      512
#define T_STEPS 256
#define NTn     8       // n tiles (512 / 64) == cluster size
#define N_TILE  64
#define NCOMP   128     // 16 clusters x 8 CTAs (fits 2 clusters-of-8 per GPC)
#define WT_STRIDE 1032  // padded row stride (halfs): conflict-free LDSM

// Global cv archive (state history), packed [par][col][m][kk][j][lane] u32
__device__ unsigned int g_statesP[2 * 16 * 16 * 32 * 4 * 32];

// ---- smem layout offsets (bytes) ----
#define SM_WT    0                        // 64 x 1032 halves = 132096
#define SM_CV    132096                   // cv stage, 16 KB
#define SM_FRESH 148480                   // fresh double buffer, 2 x 16 KB
#define SM_SMALL 181248                   // 448 floats = 1792
#define SM_SX    183040                   // 4096 (256 cells x 16 rows)
#define SM_Z     187136                   // z ring: 4 slots x 2 rows x 32 float2 = 2048
#define SM_BAR   189184                   // mbarrier
#define SM_TOTAL 189248

__device__ __forceinline__ void cp_async16(unsigned smem_addr, const void* gptr) {
    asm volatile("cp.async.cg.shared.global [%0], [%1], 16;"
                 :: "r"(smem_addr), "l"(gptr));
}
__device__ __forceinline__ void cp_commit() {
    asm volatile("cp.async.commit_group;");
}
template <int N>
__device__ __forceinline__ void cp_wait() {
    asm volatile("cp.async.wait_group %0;" :: "n"(N) : "memory");
}
__device__ __forceinline__ void mbar_init(unsigned bar, unsigned cnt) {
    asm volatile("mbarrier.init.shared.b64 [%0], %1;" :: "r"(bar), "r"(cnt) : "memory");
}
// arrive (release, cluster scope) on the bar at the SAME offset in CTA `rank`
__device__ __forceinline__ void mbar_arrive_peer(unsigned localbar, unsigned rank) {
    asm volatile(
        "{\n\t.reg .b32 ra;\n\t"
        "mapa.shared::cluster.u32 ra, %0, %1;\n\t"
        "mbarrier.arrive.release.cluster.shared::cluster.b64 _, [ra];\n\t}"
        :: "r"(localbar), "r"(rank) : "memory");
}
// wait with cluster-scope acquire (peers' DSMEM + global stores become visible)
__device__ __forceinline__ void mbar_wait_cluster(unsigned bar, unsigned parity) {
    unsigned done;
    asm volatile(
        "{\n\t.reg .pred p;\n\t"
        "mbarrier.try_wait.parity.acquire.cluster.shared::cta.b64 p, [%1], %2;\n\t"
        "selp.b32 %0, 1, 0, p;\n\t}"
        : "=r"(done) : "r"(bar), "r"(parity) : "memory");
    while (!done) {
        asm volatile(
            "{\n\t.reg .pred p;\n\t"
            "mbarrier.try_wait.parity.acquire.cluster.shared::cta.b64 p, [%1], %2, 0x989680;\n\t"
            "selp.b32 %0, 1, 0, p;\n\t}"
            : "=r"(done) : "r"(bar), "r"(parity) : "memory");
    }
}
__device__ __forceinline__ void cluster_sync() {
    asm volatile("barrier.cluster.arrive.aligned;" ::: "memory");
    asm volatile("barrier.cluster.wait.aligned;" ::: "memory");
}

__device__ __forceinline__ void mma16816(float acc[4],
    unsigned a0, unsigned a1, unsigned a2, unsigned a3,
    unsigned b0, unsigned b1)
{
    asm volatile(
        "mma.sync.aligned.m16n8k16.row.col.f32.f16.f16.f32 "
        "{%0,%1,%2,%3}, {%4,%5,%6,%7}, {%8,%9}, {%0,%1,%2,%3};"
        : "+f"(acc[0]), "+f"(acc[1]), "+f"(acc[2]), "+f"(acc[3])
        : "r"(a0), "r"(a1), "r"(a2), "r"(a3), "r"(b0), "r"(b1));
}

__device__ __forceinline__ unsigned* pslab(int par, int col) {
    return g_statesP + (((par << 4) + col) << 16);   // 65536 u32 per slab
}

// K=512 half-GEMM via ldmatrix.x4 (A packed [kk][j][lane], B = weight slice)
__device__ __forceinline__ void gemm_ldsm(unsigned aB, unsigned bB, float acc[2][4]) {
#pragma unroll 8
    for (int kk = 0; kk < 32; ++kk) {
        unsigned a0, a1, a2, a3, b0, b1, b2, b3;
        asm volatile("ldmatrix.sync.aligned.m8n8.x4.shared.b16 {%0,%1,%2,%3}, [%4];"
            : "=r"(a0), "=r"(a1), "=r"(a2), "=r"(a3) : "r"(aB));
        asm volatile("ldmatrix.sync.aligned.m8n8.x4.shared.b16 {%0,%1,%2,%3}, [%4];"
            : "=r"(b0), "=r"(b1), "=r"(b2), "=r"(b3) : "r"(bB));
        mma16816(acc[0], a0, a1, a2, a3, b0, b1);
        mma16816(acc[1], a0, a1, a2, a3, b2, b3);
        aB += 512;
        bB += 32;
    }
}

__device__ __forceinline__ float elu1(float v) {
    return v > 0.f ? v : (__expf(v) - 1.f);
}
__device__ __forceinline__ unsigned packh2(float a, float b) {
    __half2 h = __floats2half2_rn(a, b);
    return *reinterpret_cast<unsigned*>(&h);
}

__global__ void __launch_bounds__(128) rnn2d_main_kernel(
    const int* __restrict__ x,
    const float* __restrict__ Wih, const float* __restrict__ Wiv,
    const float* __restrict__ Wch, const float* __restrict__ bch,
    const float* __restrict__ Wcv, const float* __restrict__ Wout,
    const float* __restrict__ bout, float* __restrict__ out)
{
    extern __shared__ unsigned char smem[];
    __half* Wt  = (__half*)(smem + SM_WT);
    float* sWih = (float*)(smem + SM_SMALL);
    float* sWiv = sWih + 128;
    float* sBch = sWiv + 128;
    float* sWo0 = sBch + 64;
    float* sWo1 = sWo0 + 64;
    unsigned char* sx = (unsigned char*)(smem + SM_SX);
    float2* zslab = (float2*)(smem + SM_Z);     // [4 slots][2 rows][32] float2

    const int bx  = blockIdx.x;
    const int tid = threadIdx.x;
    const int m = bx >> 3, n = bx & 7;          // m-group, n-tile == cluster rank
    const int w = tid >> 5, lane = tid & 31;
    const int n0 = n * N_TILE;
    const int q = lane >> 2, tg = lane & 3;

    const unsigned sCV_s = (unsigned)__cvta_generic_to_shared(smem + SM_CV);
    const unsigned sF_s  = (unsigned)__cvta_generic_to_shared(smem + SM_FRESH);
    const unsigned wt_s  = (unsigned)__cvta_generic_to_shared(Wt);
    const unsigned zB_s  = (unsigned)__cvta_generic_to_shared(smem + SM_Z);
    const unsigned hbar  = (unsigned)__cvta_generic_to_shared(smem + SM_BAR);
    const unsigned aOff  = ((lane >> 3) << 7) + ((lane & 7) << 4);
    const unsigned brow  = 16 * w + 8 * (lane >> 4) + (lane & 7);
    const unsigned bOff  = wt_s + brow * (WT_STRIDE * 2) + (((lane >> 3) & 1) << 4);

    // resident weight slice: Wt[j][k] = W[k][n0+j]
    for (int i = tid; i < N_TILE * 1024; i += 128) {
        int j = i >> 10, k = i & 1023;
        float wv = (k < U_) ? Wch[k * U_ + n0 + j] : Wcv[(k - U_) * U_ + n0 + j];
        Wt[j * WT_STRIDE + k] = __float2half_rn(wv);
    }
    if (tid < 64) {
        sWih[tid]       = Wih[n0 + tid];
        sWih[64 + tid]  = Wih[U_ + n0 + tid];
        sWiv[tid]       = Wiv[n0 + tid];
        sWiv[64 + tid]  = Wiv[U_ + n0 + tid];
        sBch[tid]       = bch[n0 + tid];
        sWo0[tid]       = Wout[(n0 + tid) * 2 + 0];
        sWo1[tid]       = Wout[(n0 + tid) * 2 + 1];
    }
    for (int i = tid; i < 4096; i += 128) {     // spins for this CTA's 16 rows
        int rl = i & 15, cell = i >> 4;
        sx[cell * 16 + rl] = (unsigned char)x[(16 * m + rl) * 256 + cell];
    }
    if (tid == 0) mbar_init(hbar, 8);           // 8 arrivals (one per cluster CTA)
    __syncthreads();
    cluster_sync();                             // peers' bars live before any arrive

    const float bo0 = bout[0], bo1 = bout[1];
    float lp = 0.f;                             // meaningful in warp0 lanes 0,16

#pragma unroll 1
    for (int t = 1; t <= T_STEPS; ++t) {
        const int s = t - 1;
        const int r = s >> 4, p = s & 15;
        const int c  = (r & 1) ? (15 - p) : p;
        const int cp = (r & 1) ? (c + 1) : (c - 1);
        const bool has_h = (p > 0), has_v = (r > 0);

        // cv stage (prefetched at end of step t-1) ready + CTA-visible
        cp_wait<0>();
        __syncthreads();

        float acc[2][4];
#pragma unroll
        for (int f = 0; f < 2; ++f)
            acc[f][0] = acc[f][1] = acc[f][2] = acc[f][3] = 0.f;

        // old-cv GEMM (dep <= t-3) from local stage — before the fresh wait
        if (has_h && has_v)
            gemm_ldsm(sCV_s + aOff, bOff + 1024, acc);

        // fresh tile: pushed into our SMEM by cluster peers at end of step t-1
        if (t > 1) {
            mbar_wait_cluster(hbar, t & 1);
            gemm_ldsm(sF_s + ((t & 1) << 14) + aOff,
                      has_h ? bOff : bOff + 1024, acc);
        }

        // ---- epilogue
        int sLa = 0, sLb = 0, sUa = 0, sUb = 0;
        if (has_h) {
            sLa = sx[(r * 16 + cp) * 16 + q];
            sLb = sx[(r * 16 + cp) * 16 + q + 8];
        }
        if (has_v) {
            sUa = sx[((r - 1) * 16 + c) * 16 + q];
            sUb = sx[((r - 1) * 16 + c) * 16 + q + 8];
        }

        float z0a = 0.f, z1a = 0.f, z0b = 0.f, z1b = 0.f;
        unsigned pk[4];
        unsigned* Pout = pslab(r & 1, c) + (m << 12) + ((4 * n + w) << 7) + lane;
#pragma unroll
        for (int f = 0; f < 2; ++f) {
            int u0 = 16 * w + 8 * f + 2 * tg;
            float v0 = acc[f][0] + sBch[u0];
            float v1 = acc[f][1] + sBch[u0 + 1];
            float v2 = acc[f][2] + sBch[u0];
            float v3 = acc[f][3] + sBch[u0 + 1];
            if (has_h) {
                v0 += sWih[sLa * 64 + u0]; v1 += sWih[sLa * 64 + u0 + 1];
                v2 += sWih[sLb * 64 + u0]; v3 += sWih[sLb * 64 + u0 + 1];
            }
            if (has_v) {
                v0 += sWiv[sUa * 64 + u0]; v1 += sWiv[sUa * 64 + u0 + 1];
                v2 += sWiv[sUb * 64 + u0]; v3 += sWiv[sUb * 64 + u0 + 1];
            }
            v0 = elu1(v0); v1 = elu1(v1); v2 = elu1(v2); v3 = elu1(v3);

            z0a += v0 * sWo0[u0] + v1 * sWo0[u0 + 1];
            z1a += v0 * sWo1[u0] + v1 * sWo1[u0 + 1];
            z0b += v2 * sWo0[u0] + v3 * sWo0[u0 + 1];
            z1b += v2 * sWo1[u0] + v3 * sWo1[u0 + 1];

            pk[2 * f]     = packh2(v0, v1);
            pk[2 * f + 1] = packh2(v2, v3);
            Pout[(2 * f) * 32]     = pk[2 * f];       // cv archive (global)
            Pout[(2 * f + 1) * 32] = pk[2 * f + 1];
        }

        // ---- DSMEM scatter: push my 16x64 block into every peer's fresh buffer
        {
            unsigned lbase = sF_s + ((unsigned)((t + 1) & 1) << 14)
                           + ((unsigned)(4 * n + w) << 9) + ((unsigned)lane << 2);
#pragma unroll
            for (int rk = 0; rk < 8; ++rk) {
                asm volatile(
                    "{\n\t.reg .b32 pa;\n\t"
                    "mapa.shared::cluster.u32 pa, %0, %1;\n\t"
                    "st.shared::cluster.u32 [pa],     %2;\n\t"
                    "st.shared::cluster.u32 [pa+128], %3;\n\t"
                    "st.shared::cluster.u32 [pa+256], %4;\n\t"
                    "st.shared::cluster.u32 [pa+384], %5;\n\t}"
                    :: "r"(lbase), "r"(rk),
                       "r"(pk[0]), "r"(pk[1]), "r"(pk[2]), "r"(pk[3])
                    : "memory");
            }
        }

        // ---- z push (before arrive): quad-reduce, send to owner rank = row/2
        z0a += __shfl_xor_sync(0xffffffffu, z0a, 1);
        z0a += __shfl_xor_sync(0xffffffffu, z0a, 2);
        z1a += __shfl_xor_sync(0xffffffffu, z1a, 1);
        z1a += __shfl_xor_sync(0xffffffffu, z1a, 2);
        z0b += __shfl_xor_sync(0xffffffffu, z0b, 1);
        z0b += __shfl_xor_sync(0xffffffffu, z0b, 2);
        z1b += __shfl_xor_sync(0xffffffffu, z1b, 1);
        z1b += __shfl_xor_sync(0xffffffffu, z1b, 2);
        if (tg == 0) {
            unsigned zoff = zB_s + ((unsigned)(t & 3) << 9) + ((unsigned)(q & 1) << 8)
                          + ((unsigned)(4 * n + w) << 3);
            unsigned long long za, zb;
            asm("mov.b64 %0, {%1,%2};" : "=l"(za) : "f"(z0a), "f"(z1a));
            asm("mov.b64 %0, {%1,%2};" : "=l"(zb) : "f"(z0b), "f"(z1b));
            asm volatile(
                "{\n\t.reg .b32 pa;\n\t"
                "mapa.shared::cluster.u32 pa, %0, %1;\n\t"
                "st.shared::cluster.u64 [pa], %2;\n\t}"
                :: "r"(zoff), "r"(q >> 1), "l"(za) : "memory");
            asm volatile(
                "{\n\t.reg .b32 pa;\n\t"
                "mapa.shared::cluster.u32 pa, %0, %1;\n\t"
                "st.shared::cluster.u64 [pa], %2;\n\t}"
                :: "r"(zoff), "r"(4 + (q >> 1)), "l"(zb) : "memory");
        }

        __syncthreads();                 // all remote stores HB before the arrives
        if (tid < 8) mbar_arrive_peer(hbar, (unsigned)tid);

        // ---- tail: warp0 reduces z slot of step t-1 (visible via wait(t) acquire)
        if (w == 0 && t >= 2) {
            int u = t - 1;
            int su = u - 1, ru = su >> 4, pu = su & 15;
            int cu = (ru & 1) ? (15 - pu) : pu;
            int row = lane >> 4, idx = lane & 15;
            const float2* zp = zslab + ((u & 3) << 6) + (row << 5) + idx;
            float2 va = zp[0], vb = zp[16];
            float zz0 = va.x + vb.x, zz1 = va.y + vb.y;
            zz0 += __shfl_xor_sync(0xffffffffu, zz0, 1);
            zz1 += __shfl_xor_sync(0xffffffffu, zz1, 1);
            zz0 += __shfl_xor_sync(0xffffffffu, zz0, 2);
            zz1 += __shfl_xor_sync(0xffffffffu, zz1, 2);
            zz0 += __shfl_xor_sync(0xffffffffu, zz0, 4);
            zz1 += __shfl_xor_sync(0xffffffffu, zz1, 4);
            zz0 += __shfl_xor_sync(0xffffffffu, zz0, 8);
            zz1 += __shfl_xor_sync(0xffffffffu, zz1, 8);
            if (idx == 0) {
                float f0 = bo0 + zz0, f1 = bo1 + zz1;
                int spin = sx[(ru * 16 + cu) * 16 + 2 * n + row];
                float mz = fmaxf(f0, f1);
                float lse = mz + logf(expf(f0 - mz) + expf(f1 - mz));
                lp += (spin ? f1 : f0) - lse;
            }
        }

        // ---- cv prefetch for step t+1 (dep <= t-1, visible via barrier chain)
        if (t < T_STEPS) {
            int r2 = t >> 4, p2 = t & 15;
            if (p2 >= 1 && r2 >= 1) {
                int c2 = (r2 & 1) ? (15 - p2) : p2;
                const unsigned* src = pslab((r2 - 1) & 1, c2) + (m << 12);
#pragma unroll
                for (int i = 0; i < 8; ++i)
                    cp_async16(sCV_s + tid * 16 + i * 2048, src + tid * 4 + i * 512);
            }
            cp_commit();
        }
    }

    // final: wait for completion #256 (parity 1), reduce step 256's slot, output
    mbar_wait_cluster(hbar, 1);
    if (w == 0) {
        int u = T_STEPS;
        int su = u - 1, ru = su >> 4, pu = su & 15;
        int cu = (ru & 1) ? (15 - pu) : pu;
        int row = lane >> 4, idx = lane & 15;
        const float2* zp = zslab + ((u & 3) << 6) + (row << 5) + idx;
        float2 va = zp[0], vb = zp[16];
        float zz0 = va.x + vb.x, zz1 = va.y + vb.y;
        zz0 += __shfl_xor_sync(0xffffffffu, zz0, 1);
        zz1 += __shfl_xor_sync(0xffffffffu, zz1, 1);
        zz0 += __shfl_xor_sync(0xffffffffu, zz0, 2);
        zz1 += __shfl_xor_sync(0xffffffffu, zz1, 2);
        zz0 += __shfl_xor_sync(0xffffffffu, zz0, 4);
        zz1 += __shfl_xor_sync(0xffffffffu, zz1, 4);
        zz0 += __shfl_xor_sync(0xffffffffu, zz0, 8);
        zz1 += __shfl_xor_sync(0xffffffffu, zz1, 8);
        if (idx == 0) {
            float f0 = bo0 + zz0, f1 = bo1 + zz1;
            int spin = sx[(ru * 16 + cu) * 16 + 2 * n + row];
            float mz = fmaxf(f0, f1);
            float lse = mz + logf(expf(f0 - mz) + expf(f1 - mz));
            lp += (spin ? f1 : f0) - lse;
            out[16 * m + 2 * n + row] = lp;
        }
    }
    cluster_sync();
}

extern "C" void kernel_launch(void* const* d_in, const int* in_sizes, int n_in,
                              void* d_out, int out_size)
{
    (void)in_sizes; (void)n_in; (void)out_size;
    const int*   x    = (const int*)  d_in[0];
    const float* Wih  = (const float*)d_in[1];
    const float* Wiv  = (const float*)d_in[2];
    const float* Wch  = (const float*)d_in[3];
    const float* bch  = (const float*)d_in[4];
    const float* Wcv  = (const float*)d_in[5];
    const float* Wout = (const float*)d_in[6];
    const float* bout = (const float*)d_in[7];
    float* out = (float*)d_out;

    cudaFuncSetAttribute(rnn2d_main_kernel,
                         cudaFuncAttributeMaxDynamicSharedMemorySize, SM_TOTAL);

    cudaLaunchConfig_t cfg = {};
    cfg.gridDim  = dim3(NCOMP, 1, 1);            // 128 = 16 clusters of 8
    cfg.blockDim = dim3(128, 1, 1);
    cfg.dynamicSmemBytes = SM_TOTAL;
    cudaLaunchAttribute attrs[1];
    attrs[0].id = cudaLaunchAttributeClusterDimension;
    attrs[0].val.clusterDim = {8, 1, 1};
    cfg.attrs = attrs;
    cfg.numAttrs = 1;
    cudaLaunchKernelEx(&cfg, rnn2d_main_kernel,
                       x, Wih, Wiv, Wch, bch, Wcv, Wout, bout, out);
}

// round 11
// speedup vs baseline: 1.8030x; 1.8030x over previous
#include <cuda_runtime.h>
#include <cuda_fp16.h>
#include <math.h>

// Problem constants
#define B_      256
#define U_      512
#define T_STEPS 256
#define NTn     8       // n tiles (512 / 64)
#define N_TILE  64
#define NCOMP   128     // compute CTAs (16 m-groups x 8 n-tiles)
#define NRED    8       // reducer CTAs
#define THREADS 256
#define WT_STRIDE 1032  // padded row stride (halfs): conflict-free LDSM
#define ZDEPTH  8

// Packed hidden-state storage: slab(par,col) = [m=16][kk=32][j=4][lane=32] u32
__device__ unsigned int g_statesP[2 * 16 * 16 * 32 * 4 * 32];
// logit partials: [ZDEPTH][NTn][4 warps][B] float2
__device__ float2 g_zpart[ZDEPTH * NTn * 4 * B_];
// per-CTA completed-step counters (8 per m-group), reducer flags
__device__ int g_flags[NCOMP];
__device__ int g_rflags[NRED];

// ---- smem layout offsets (bytes) ----
#define SM_WT    0                       // 64 x 1032 halves = 132096
#define SM_CV    132096                  // cv stage, 16 KB
#define SM_FR    148480                  // fresh stage, 16 KB
#define SM_PART  164864                  // cv fp32 partials, 4 KB
#define SM_SMALL 168960                  // 448 floats = 1792
#define SM_SX    170752                  // 8192 (reducers cache 32 rows!)
#define SM_TOTAL 178944

__device__ __forceinline__ int ld_acquire(const int* p) {
    int v;
    asm volatile("ld.global.acquire.gpu.b32 %0, [%1];" : "=r"(v) : "l"(p) : "memory");
    return v;
}
__device__ __forceinline__ void st_release(int* p, int v) {
    asm volatile("st.global.release.gpu.b32 [%0], %1;" :: "l"(p), "r"(v) : "memory");
}
__device__ __forceinline__ float2 ldg_cg_f2(const float2* p) {
    float2 v;
    asm volatile("ld.global.cg.v2.f32 {%0,%1}, [%2];" : "=f"(v.x), "=f"(v.y) : "l"(p));
    return v;
}
__device__ __forceinline__ void cp_async16(unsigned smem_addr, const void* gptr) {
    asm volatile("cp.async.cg.shared.global [%0], [%1], 16;"
                 :: "r"(smem_addr), "l"(gptr));
}
__device__ __forceinline__ void cp_commit() {
    asm volatile("cp.async.commit_group;");
}
template <int N>
__device__ __forceinline__ void cp_wait() {
    asm volatile("cp.async.wait_group %0;" :: "n"(N) : "memory");
}
__device__ __forceinline__ void bar_sync(int id, int cnt) {
    asm volatile("bar.sync %0, %1;" :: "r"(id), "r"(cnt) : "memory");
}

__device__ __forceinline__ void mma16816(float acc[4],
    unsigned a0, unsigned a1, unsigned a2, unsigned a3,
    unsigned b0, unsigned b1)
{
    asm volatile(
        "mma.sync.aligned.m16n8k16.row.col.f32.f16.f16.f32 "
        "{%0,%1,%2,%3}, {%4,%5,%6,%7}, {%8,%9}, {%0,%1,%2,%3};"
        : "+f"(acc[0]), "+f"(acc[1]), "+f"(acc[2]), "+f"(acc[3])
        : "r"(a0), "r"(a1), "r"(a2), "r"(a3), "r"(b0), "r"(b1));
}

__device__ __forceinline__ unsigned* pslab(int par, int col) {
    return g_statesP + (((par << 4) + col) << 16);   // 65536 u32 per slab
}

// K=512 half-GEMM via ldmatrix.x4 (A packed [kk][j][lane], B = weight slice)
__device__ __forceinline__ void gemm_ldsm(unsigned aB, unsigned bB, float acc[2][4]) {
#pragma unroll 8
    for (int kk = 0; kk < 32; ++kk) {
        unsigned a0, a1, a2, a3, b0, b1, b2, b3;
        asm volatile("ldmatrix.sync.aligned.m8n8.x4.shared.b16 {%0,%1,%2,%3}, [%4];"
            : "=r"(a0), "=r"(a1), "=r"(a2), "=r"(a3) : "r"(aB));
        asm volatile("ldmatrix.sync.aligned.m8n8.x4.shared.b16 {%0,%1,%2,%3}, [%4];"
            : "=r"(b0), "=r"(b1), "=r"(b2), "=r"(b3) : "r"(bB));
        mma16816(acc[0], a0, a1, a2, a3, b0, b1);
        mma16816(acc[1], a0, a1, a2, a3, b2, b3);
        aB += 512;
        bB += 32;
    }
}

__device__ __forceinline__ float elu1(float v) {
    return v > 0.f ? v : (__expf(v) - 1.f);
}
__device__ __forceinline__ unsigned packh2(float a, float b) {
    __half2 h = __floats2half2_rn(a, b);
    return *reinterpret_cast<unsigned*>(&h);
}

__global__ void rnn2d_init_kernel() {
    if (threadIdx.x < NCOMP) g_flags[threadIdx.x] = 0;
    if (threadIdx.x < NRED)  g_rflags[threadIdx.x] = 0;
}

__global__ void __launch_bounds__(THREADS) rnn2d_main_kernel(
    const int* __restrict__ x,
    const float* __restrict__ Wih, const float* __restrict__ Wiv,
    const float* __restrict__ Wch, const float* __restrict__ bch,
    const float* __restrict__ Wcv, const float* __restrict__ Wout,
    const float* __restrict__ bout, float* __restrict__ out)
{
    extern __shared__ unsigned char smem[];
    __half* Wt   = (__half*)(smem + SM_WT);
    float*  sPart= (float*)(smem + SM_PART);     // [4 warps][32 lanes][8]
    float* sWih  = (float*)(smem + SM_SMALL);
    float* sWiv  = sWih + 128;
    float* sBch  = sWiv + 128;
    float* sWo0  = sBch + 64;
    float* sWo1  = sWo0 + 64;
    unsigned char* sx = (unsigned char*)(smem + SM_SX);

    const int bx  = blockIdx.x;
    const int tid = threadIdx.x;

    if (bx >= NCOMP) {
        // ---------------- reducer CTA (off the critical path) ----------------
        const int mr = bx - NCOMP;                 // rows 32*mr .. 32*mr+31
        for (int i = tid; i < 8192; i += THREADS) {
            int rl = i & 31, cell = i >> 5;
            sx[cell * 32 + rl] = (unsigned char)x[(32 * mr + rl) * 256 + cell];
        }
        __syncthreads();
        if (tid >= 32) return;

        const int lane = tid;
        const int b = 32 * mr + lane;
        const float bo0 = bout[0], bo1 = bout[1];
        int* myflags = g_flags + 16 * mr;          // 2 m-groups x 8 flags
        float lp = 0.f;
        for (int t = 1; t <= T_STEPS; ++t) {
            if (lane < 16) {
                while (ld_acquire(myflags + lane) < t) { }
            }
            __syncwarp();
            asm volatile("membar.gl;" ::: "memory");
            float z0 = bo0, z1 = bo1;
            const float2* zp = g_zpart + (t & (ZDEPTH - 1)) * (NTn * 4 * B_) + b;
#pragma unroll
            for (int i = 0; i < 32; ++i) {
                float2 v = ldg_cg_f2(zp + i * B_);
                z0 += v.x; z1 += v.y;
            }
            int s = t - 1, r = s >> 4, p = s & 15;
            int c = (r & 1) ? (15 - p) : p;
            int spin = sx[(r * 16 + c) * 32 + lane];
            float mz = fmaxf(z0, z1);
            float lse = mz + logf(expf(z0 - mz) + expf(z1 - mz));
            lp += (spin ? z1 : z0) - lse;
            __syncwarp();
            if (lane == 0) st_release(&g_rflags[mr], t);
        }
        out[b] = lp;
        return;
    }

    // ---------------- compute CTA ----------------
    const int m = bx >> 3, n = bx & 7;           // 16-row group, 64-col tile
    const int w = tid >> 5, lane = tid & 31;
    const int wc = w & 3;                        // column group (16 cols)
    const bool isF = (w < 4);                    // fresh group vs cv group
    const int n0 = n * N_TILE;
    const int q = lane >> 2, tg = lane & 3;

    const unsigned sCV_s = (unsigned)__cvta_generic_to_shared(smem + SM_CV);
    const unsigned sFR_s = (unsigned)__cvta_generic_to_shared(smem + SM_FR);
    const unsigned wt_s  = (unsigned)__cvta_generic_to_shared(Wt);
    const unsigned aOff  = ((lane >> 3) << 7) + ((lane & 7) << 4);
    const unsigned brow  = 16 * wc + 8 * (lane >> 4) + (lane & 7);
    const unsigned bOff  = wt_s + brow * (WT_STRIDE * 2) + (((lane >> 3) & 1) << 4);

    // resident weight slice: Wt[j][k] = W[k][n0+j]
    for (int i = tid; i < N_TILE * 1024; i += THREADS) {
        int j = i >> 10, k = i & 1023;
        float wv = (k < U_) ? Wch[k * U_ + n0 + j] : Wcv[(k - U_) * U_ + n0 + j];
        Wt[j * WT_STRIDE + k] = __float2half_rn(wv);
    }
    if (tid < 64) {
        sWih[tid]       = Wih[n0 + tid];
        sWih[64 + tid]  = Wih[U_ + n0 + tid];
        sWiv[tid]       = Wiv[n0 + tid];
        sWiv[64 + tid]  = Wiv[U_ + n0 + tid];
        sBch[tid]       = bch[n0 + tid];
        sWo0[tid]       = Wout[(n0 + tid) * 2 + 0];
        sWo1[tid]       = Wout[(n0 + tid) * 2 + 1];
    }
    for (int i = tid; i < 4096; i += THREADS) {  // spins for this CTA's 16 rows
        int rl = i & 15, cell = i >> 4;
        sx[cell * 16 + rl] = (unsigned char)x[(16 * m + rl) * 256 + cell];
    }
    __syncthreads();

    int* myflags = g_flags + m * 8;

#pragma unroll 1
    for (int t = 1; t <= T_STEPS; ++t) {
        const int s = t - 1;
        const int r = s >> 4, p = s & 15;
        const int c  = (r & 1) ? (15 - p) : p;
        const int cp = (r & 1) ? (c + 1) : (c - 1);
        const bool has_h = (p > 0), has_v = (r > 0);
        const bool oldcv = has_h && has_v;       // old-cv GEMM active this step

        // cv stage (prefetched by cv group at end of t-1) ready + CTA-visible
        cp_wait<0>();
        __syncthreads();

        if (isF) {
            // ======== FRESH GROUP (warps 0-3, tid 0..127) ========
            if (w == 0 && t > 1) {
                if (lane < 8) {
                    while (ld_acquire(myflags + lane) < t - 1) { }
                }
                if (lane == 8 && t > ZDEPTH) {
                    while (ld_acquire(&g_rflags[m >> 1]) < t - ZDEPTH) { }
                }
            }
            bar_sync(1, 128);                    // deps acquired (fresh group)

            float acc[2][4];
#pragma unroll
            for (int f = 0; f < 2; ++f)
                acc[f][0] = acc[f][1] = acc[f][2] = acc[f][3] = 0.f;

            if (t > 1) {
                const unsigned* fsrc = has_h ? (pslab(r & 1, cp) + (m << 12))
                                             : (pslab((r - 1) & 1, c) + (m << 12));
#pragma unroll
                for (int i = 0; i < 8; ++i)
                    cp_async16(sFR_s + tid * 16 + i * 2048, fsrc + tid * 4 + i * 512);
                cp_commit();
                cp_wait<0>();
                bar_sync(1, 128);                // fresh tile staged
                gemm_ldsm(sFR_s + aOff, has_h ? bOff : bOff + 1024, acc);
            }

            __syncthreads();                     // join: cv partials are in SMEM

            if (oldcv) {
                const float4* pp = (const float4*)(sPart + (wc * 32 + lane) * 8);
                float4 pa = pp[0], pb = pp[1];
                acc[0][0] += pa.x; acc[0][1] += pa.y; acc[0][2] += pa.z; acc[0][3] += pa.w;
                acc[1][0] += pb.x; acc[1][1] += pb.y; acc[1][2] += pb.z; acc[1][3] += pb.w;
            }

            // ---- epilogue
            int sLa = 0, sLb = 0, sUa = 0, sUb = 0;
            if (has_h) {
                sLa = sx[(r * 16 + cp) * 16 + q];
                sLb = sx[(r * 16 + cp) * 16 + q + 8];
            }
            if (has_v) {
                sUa = sx[((r - 1) * 16 + c) * 16 + q];
                sUb = sx[((r - 1) * 16 + c) * 16 + q + 8];
            }

            float z0a = 0.f, z1a = 0.f, z0b = 0.f, z1b = 0.f;
            unsigned* Pout = pslab(r & 1, c) + (m << 12) + ((4 * n + w) << 7) + lane;
#pragma unroll
            for (int f = 0; f < 2; ++f) {
                int u0 = 16 * w + 8 * f + 2 * tg;
                float v0 = acc[f][0] + sBch[u0];
                float v1 = acc[f][1] + sBch[u0 + 1];
                float v2 = acc[f][2] + sBch[u0];
                float v3 = acc[f][3] + sBch[u0 + 1];
                if (has_h) {
                    v0 += sWih[sLa * 64 + u0]; v1 += sWih[sLa * 64 + u0 + 1];
                    v2 += sWih[sLb * 64 + u0]; v3 += sWih[sLb * 64 + u0 + 1];
                }
                if (has_v) {
                    v0 += sWiv[sUa * 64 + u0]; v1 += sWiv[sUa * 64 + u0 + 1];
                    v2 += sWiv[sUb * 64 + u0]; v3 += sWiv[sUb * 64 + u0 + 1];
                }
                v0 = elu1(v0); v1 = elu1(v1); v2 = elu1(v2); v3 = elu1(v3);

                z0a += v0 * sWo0[u0] + v1 * sWo0[u0 + 1];
                z1a += v0 * sWo1[u0] + v1 * sWo1[u0 + 1];
                z0b += v2 * sWo0[u0] + v3 * sWo0[u0 + 1];
                z1b += v2 * sWo1[u0] + v3 * sWo1[u0 + 1];

                Pout[(2 * f) * 32]     = packh2(v0, v1);
                Pout[(2 * f + 1) * 32] = packh2(v2, v3);
            }

            // z quad-reduce + store (reducer consumers)
            z0a += __shfl_xor_sync(0xffffffffu, z0a, 1);
            z0a += __shfl_xor_sync(0xffffffffu, z0a, 2);
            z1a += __shfl_xor_sync(0xffffffffu, z1a, 1);
            z1a += __shfl_xor_sync(0xffffffffu, z1a, 2);
            z0b += __shfl_xor_sync(0xffffffffu, z0b, 1);
            z0b += __shfl_xor_sync(0xffffffffu, z0b, 2);
            z1b += __shfl_xor_sync(0xffffffffu, z1b, 1);
            z1b += __shfl_xor_sync(0xffffffffu, z1b, 2);
            if (tg == 0) {
                float2* zp = g_zpart + (((t & (ZDEPTH - 1)) * NTn + n) * 4 + w) * B_;
                int bA = 16 * m + q;
                zp[bA]     = make_float2(z0a, z1a);
                zp[bA + 8] = make_float2(z0b, z1b);
            }

            bar_sync(1, 128);                    // all fresh stores done
            if (tid == 0) st_release(&g_flags[bx], t);
        } else {
            // ======== CV GROUP (warps 4-7, tid 128..255) ========
            if (oldcv) {
                float acc[2][4];
#pragma unroll
                for (int f = 0; f < 2; ++f)
                    acc[f][0] = acc[f][1] = acc[f][2] = acc[f][3] = 0.f;
                gemm_ldsm(sCV_s + aOff, bOff + 1024, acc);
                float4* pp = (float4*)(sPart + (wc * 32 + lane) * 8);
                pp[0] = make_float4(acc[0][0], acc[0][1], acc[0][2], acc[0][3]);
                pp[1] = make_float4(acc[1][0], acc[1][1], acc[1][2], acc[1][3]);
            }
            bar_sync(2, 128);                    // cv group done reading sCV

            // prefetch next step's old-cv tile into sCV
            if (t < T_STEPS) {
                int r2 = t >> 4, p2 = t & 15;
                if (p2 >= 1 && r2 >= 1) {
                    int c2 = (r2 & 1) ? (15 - p2) : p2;
                    const unsigned* src = pslab((r2 - 1) & 1, c2) + (m << 12);
                    int tl = tid - 128;
#pragma unroll
                    for (int i = 0; i < 8; ++i)
                        cp_async16(sCV_s + tl * 16 + i * 2048, src + tl * 4 + i * 512);
                }
                cp_commit();
            }

            __syncthreads();                     // join (partials visible to fresh)
        }
    }
}

extern "C" void kernel_launch(void* const* d_in, const int* in_sizes, int n_in,
                              void* d_out, int out_size)
{
    (void)in_sizes; (void)n_in; (void)out_size;
    const int*   x    = (const int*)  d_in[0];
    const float* Wih  = (const float*)d_in[1];
    const float* Wiv  = (const float*)d_in[2];
    const float* Wch  = (const float*)d_in[3];
    const float* bch  = (const float*)d_in[4];
    const float* Wcv  = (const float*)d_in[5];
    const float* Wout = (const float*)d_in[6];
    const float* bout = (const float*)d_in[7];
    float* out = (float*)d_out;

    cudaFuncSetAttribute(rnn2d_main_kernel,
                         cudaFuncAttributeMaxDynamicSharedMemorySize, SM_TOTAL);

    rnn2d_init_kernel<<<1, 128>>>();
    rnn2d_main_kernel<<<NCOMP + NRED, THREADS, SM_TOTAL>>>(
        x, Wih, Wiv, Wch, bch, Wcv, Wout, bout, out);
}

// round 12
// speedup vs baseline: 1.8220x; 1.0105x over previous
#include <cuda_runtime.h>
#include <cuda_fp16.h>
#include <math.h>

// Problem constants
#define B_      256
#define U_      512
#define T_STEPS 256
#define NTn     8       // n tiles (512 / 64)
#define N_TILE  64
#define NCOMP   128     // compute CTAs (16 m-groups x 8 n-tiles)
#define NRED    8       // reducer CTAs
#define THREADS 256
#define WT_STRIDE 1032  // padded row stride (halfs): conflict-free LDSM
#define ZDEPTH  8

// Packed hidden-state storage: slab(par,col) = [m=16][kk=32][j=4][lane=32] u32
__device__ unsigned int g_statesP[2 * 16 * 16 * 32 * 4 * 32];
// logit partials: [ZDEPTH][NTn][4 warps][B] float2
__device__ float2 g_zpart[ZDEPTH * NTn * 4 * B_];
// per-CTA completed-step counters (8 per m-group), reducer flags
__device__ int g_flags[NCOMP];
__device__ int g_rflags[NRED];

// ---- smem layout offsets (bytes) ----
#define SM_WT    0                       // 64 x 1032 halves = 132096
#define SM_CV    132096                  // cv stage, 16 KB
#define SM_FR    148480                  // fresh stage, 16 KB
#define SM_PART  164864                  // cv fp32 partials, double buffered, 8 KB
#define SM_SMALL 173056                  // 448 floats = 1792
#define SM_SX    174848                  // 8192 (reducers cache 32 rows)
#define SM_TOTAL 183040

__device__ __forceinline__ int ld_acquire(const int* p) {
    int v;
    asm volatile("ld.global.acquire.gpu.b32 %0, [%1];" : "=r"(v) : "l"(p) : "memory");
    return v;
}
__device__ __forceinline__ void st_release(int* p, int v) {
    asm volatile("st.global.release.gpu.b32 [%0], %1;" :: "l"(p), "r"(v) : "memory");
}
__device__ __forceinline__ float2 ldg_cg_f2(const float2* p) {
    float2 v;
    asm volatile("ld.global.cg.v2.f32 {%0,%1}, [%2];" : "=f"(v.x), "=f"(v.y) : "l"(p));
    return v;
}
__device__ __forceinline__ void cp_async16(unsigned smem_addr, const void* gptr) {
    asm volatile("cp.async.cg.shared.global [%0], [%1], 16;"
                 :: "r"(smem_addr), "l"(gptr));
}
__device__ __forceinline__ void cp_commit() {
    asm volatile("cp.async.commit_group;");
}
template <int N>
__device__ __forceinline__ void cp_wait() {
    asm volatile("cp.async.wait_group %0;" :: "n"(N) : "memory");
}
__device__ __forceinline__ void bar_sync(int id, int cnt) {
    asm volatile("bar.sync %0, %1;" :: "r"(id), "r"(cnt) : "memory");
}

__device__ __forceinline__ void mma16816(float acc[4],
    unsigned a0, unsigned a1, unsigned a2, unsigned a3,
    unsigned b0, unsigned b1)
{
    asm volatile(
        "mma.sync.aligned.m16n8k16.row.col.f32.f16.f16.f32 "
        "{%0,%1,%2,%3}, {%4,%5,%6,%7}, {%8,%9}, {%0,%1,%2,%3};"
        : "+f"(acc[0]), "+f"(acc[1]), "+f"(acc[2]), "+f"(acc[3])
        : "r"(a0), "r"(a1), "r"(a2), "r"(a3), "r"(b0), "r"(b1));
}

__device__ __forceinline__ unsigned* pslab(int par, int col) {
    return g_statesP + (((par << 4) + col) << 16);   // 65536 u32 per slab
}

// KKN-step half-GEMM via ldmatrix.x4 (A packed [kk][j][lane], B = weight slice)
template <int KKN>
__device__ __forceinline__ void gemm_ldsm_n(unsigned aB, unsigned bB, float acc[2][4]) {
#pragma unroll 8
    for (int kk = 0; kk < KKN; ++kk) {
        unsigned a0, a1, a2, a3, b0, b1, b2, b3;
        asm volatile("ldmatrix.sync.aligned.m8n8.x4.shared.b16 {%0,%1,%2,%3}, [%4];"
            : "=r"(a0), "=r"(a1), "=r"(a2), "=r"(a3) : "r"(aB));
        asm volatile("ldmatrix.sync.aligned.m8n8.x4.shared.b16 {%0,%1,%2,%3}, [%4];"
            : "=r"(b0), "=r"(b1), "=r"(b2), "=r"(b3) : "r"(bB));
        mma16816(acc[0], a0, a1, a2, a3, b0, b1);
        mma16816(acc[1], a0, a1, a2, a3, b2, b3);
        aB += 512;
        bB += 32;
    }
}

__device__ __forceinline__ float elu1(float v) {
    return v > 0.f ? v : (__expf(v) - 1.f);
}
__device__ __forceinline__ unsigned packh2(float a, float b) {
    __half2 h = __floats2half2_rn(a, b);
    return *reinterpret_cast<unsigned*>(&h);
}

__global__ void rnn2d_init_kernel() {
    if (threadIdx.x < NCOMP) g_flags[threadIdx.x] = 0;
    if (threadIdx.x < NRED)  g_rflags[threadIdx.x] = 0;
}

__global__ void __launch_bounds__(THREADS) rnn2d_main_kernel(
    const int* __restrict__ x,
    const float* __restrict__ Wih, const float* __restrict__ Wiv,
    const float* __restrict__ Wch, const float* __restrict__ bch,
    const float* __restrict__ Wcv, const float* __restrict__ Wout,
    const float* __restrict__ bout, float* __restrict__ out)
{
    extern __shared__ unsigned char smem[];
    __half* Wt   = (__half*)(smem + SM_WT);
    float*  sPart= (float*)(smem + SM_PART);     // [2 par][4 warps][32 lanes][8]
    float* sWih  = (float*)(smem + SM_SMALL);
    float* sWiv  = sWih + 128;
    float* sBch  = sWiv + 128;
    float* sWo0  = sBch + 64;
    float* sWo1  = sWo0 + 64;
    unsigned char* sx = (unsigned char*)(smem + SM_SX);

    const int bx  = blockIdx.x;
    const int tid = threadIdx.x;

    if (bx >= NCOMP) {
        // ---------------- reducer CTA (off the critical path) ----------------
        const int mr = bx - NCOMP;                 // rows 32*mr .. 32*mr+31
        for (int i = tid; i < 8192; i += THREADS) {
            int rl = i & 31, cell = i >> 5;
            sx[cell * 32 + rl] = (unsigned char)x[(32 * mr + rl) * 256 + cell];
        }
        __syncthreads();
        if (tid >= 32) return;

        const int lane = tid;
        const int b = 32 * mr + lane;
        const float bo0 = bout[0], bo1 = bout[1];
        int* myflags = g_flags + 16 * mr;          // 2 m-groups x 8 flags
        float lp = 0.f;
        for (int t = 1; t <= T_STEPS; ++t) {
            if (lane < 16) {
                while (ld_acquire(myflags + lane) < t) { }
            }
            __syncwarp();
            asm volatile("membar.gl;" ::: "memory");
            float z0 = bo0, z1 = bo1;
            const float2* zp = g_zpart + (t & (ZDEPTH - 1)) * (NTn * 4 * B_) + b;
#pragma unroll
            for (int i = 0; i < 32; ++i) {
                float2 v = ldg_cg_f2(zp + i * B_);
                z0 += v.x; z1 += v.y;
            }
            int s = t - 1, r = s >> 4, p = s & 15;
            int c = (r & 1) ? (15 - p) : p;
            int spin = sx[(r * 16 + c) * 32 + lane];
            float mz = fmaxf(z0, z1);
            float lse = mz + logf(expf(z0 - mz) + expf(z1 - mz));
            lp += (spin ? z1 : z0) - lse;
            __syncwarp();
            if (lane == 0) st_release(&g_rflags[mr], t);
        }
        out[b] = lp;
        return;
    }

    // ---------------- compute CTA ----------------
    const int m = bx >> 3, n = bx & 7;           // 16-row group, 64-col tile
    const int w = tid >> 5, lane = tid & 31;
    const int wc = w & 3;                        // column group (16 cols)
    const bool isF = (w < 4);                    // fresh group vs cv group
    const int n0 = n * N_TILE;
    const int q = lane >> 2, tg = lane & 3;

    const unsigned sCV_s = (unsigned)__cvta_generic_to_shared(smem + SM_CV);
    const unsigned sFR_s = (unsigned)__cvta_generic_to_shared(smem + SM_FR);
    const unsigned wt_s  = (unsigned)__cvta_generic_to_shared(Wt);
    const unsigned aOff  = ((lane >> 3) << 7) + ((lane & 7) << 4);
    const unsigned brow  = 16 * wc + 8 * (lane >> 4) + (lane & 7);
    const unsigned bOff  = wt_s + brow * (WT_STRIDE * 2) + (((lane >> 3) & 1) << 4);

    // resident weight slice: Wt[j][k] = W[k][n0+j]
    for (int i = tid; i < N_TILE * 1024; i += THREADS) {
        int j = i >> 10, k = i & 1023;
        float wv = (k < U_) ? Wch[k * U_ + n0 + j] : Wcv[(k - U_) * U_ + n0 + j];
        Wt[j * WT_STRIDE + k] = __float2half_rn(wv);
    }
    if (tid < 64) {
        sWih[tid]       = Wih[n0 + tid];
        sWih[64 + tid]  = Wih[U_ + n0 + tid];
        sWiv[tid]       = Wiv[n0 + tid];
        sWiv[64 + tid]  = Wiv[U_ + n0 + tid];
        sBch[tid]       = bch[n0 + tid];
        sWo0[tid]       = Wout[(n0 + tid) * 2 + 0];
        sWo1[tid]       = Wout[(n0 + tid) * 2 + 1];
    }
    for (int i = tid; i < 4096; i += THREADS) {  // spins for this CTA's 16 rows
        int rl = i & 15, cell = i >> 4;
        sx[cell * 16 + rl] = (unsigned char)x[(16 * m + rl) * 256 + cell];
    }
    __syncthreads();

    int* myflags = g_flags + m * 8;

#pragma unroll 1
    for (int t = 1; t <= T_STEPS; ++t) {
        const int s = t - 1;
        const int r = s >> 4, p = s & 15;
        const int c  = (r & 1) ? (15 - p) : p;
        const int cp = (r & 1) ? (c + 1) : (c - 1);
        const bool has_h = (p > 0), has_v = (r > 0);
        const bool oldcv = has_h && has_v;       // old-cv GEMM active this step
        float* sP = sPart + (t & 1) * 1024;      // parity-selected partial buffer

        if (isF) {
            // ======== FRESH GROUP (warps 0-3, tid 0..127) ========
            if (w == 0 && t > 1) {
                if (lane < 8) {
                    while (ld_acquire(myflags + lane) < t - 1) { }
                }
                if (lane == 8 && t > ZDEPTH) {
                    while (ld_acquire(&g_rflags[m >> 1]) < t - ZDEPTH) { }
                }
            }
            bar_sync(1, 128);                    // deps acquired (fresh group)

            float acc[2][4];
#pragma unroll
            for (int f = 0; f < 2; ++f)
                acc[f][0] = acc[f][1] = acc[f][2] = acc[f][3] = 0.f;

            if (t > 1) {
                const unsigned* fsrc = has_h ? (pslab(r & 1, cp) + (m << 12))
                                             : (pslab((r - 1) & 1, c) + (m << 12));
                // two 8KB chunks -> copy/GEMM overlap
#pragma unroll
                for (int i = 0; i < 4; ++i)
                    cp_async16(sFR_s + tid * 16 + i * 2048, fsrc + tid * 4 + i * 512);
                cp_commit();
#pragma unroll
                for (int i = 4; i < 8; ++i)
                    cp_async16(sFR_s + tid * 16 + i * 2048, fsrc + tid * 4 + i * 512);
                cp_commit();

                const unsigned bB = has_h ? bOff : bOff + 1024;
                cp_wait<1>();
                bar_sync(1, 128);                // first half staged
                gemm_ldsm_n<16>(sFR_s + aOff, bB, acc);
                cp_wait<0>();
                bar_sync(1, 128);                // second half staged
                gemm_ldsm_n<16>(sFR_s + 8192 + aOff, bB + 512, acc);
            }

            __syncthreads();                     // join: cv partials in sPart[par]

            if (oldcv) {
                const float4* pp = (const float4*)(sP + (wc * 32 + lane) * 8);
                float4 pa = pp[0], pb = pp[1];
                acc[0][0] += pa.x; acc[0][1] += pa.y; acc[0][2] += pa.z; acc[0][3] += pa.w;
                acc[1][0] += pb.x; acc[1][1] += pb.y; acc[1][2] += pb.z; acc[1][3] += pb.w;
            }

            // ---- epilogue
            int sLa = 0, sLb = 0, sUa = 0, sUb = 0;
            if (has_h) {
                sLa = sx[(r * 16 + cp) * 16 + q];
                sLb = sx[(r * 16 + cp) * 16 + q + 8];
            }
            if (has_v) {
                sUa = sx[((r - 1) * 16 + c) * 16 + q];
                sUb = sx[((r - 1) * 16 + c) * 16 + q + 8];
            }

            float z0a = 0.f, z1a = 0.f, z0b = 0.f, z1b = 0.f;
            unsigned* Pout = pslab(r & 1, c) + (m << 12) + ((4 * n + w) << 7) + lane;
#pragma unroll
            for (int f = 0; f < 2; ++f) {
                int u0 = 16 * w + 8 * f + 2 * tg;
                float v0 = acc[f][0] + sBch[u0];
                float v1 = acc[f][1] + sBch[u0 + 1];
                float v2 = acc[f][2] + sBch[u0];
                float v3 = acc[f][3] + sBch[u0 + 1];
                if (has_h) {
                    v0 += sWih[sLa * 64 + u0]; v1 += sWih[sLa * 64 + u0 + 1];
                    v2 += sWih[sLb * 64 + u0]; v3 += sWih[sLb * 64 + u0 + 1];
                }
                if (has_v) {
                    v0 += sWiv[sUa * 64 + u0]; v1 += sWiv[sUa * 64 + u0 + 1];
                    v2 += sWiv[sUb * 64 + u0]; v3 += sWiv[sUb * 64 + u0 + 1];
                }
                v0 = elu1(v0); v1 = elu1(v1); v2 = elu1(v2); v3 = elu1(v3);

                z0a += v0 * sWo0[u0] + v1 * sWo0[u0 + 1];
                z1a += v0 * sWo1[u0] + v1 * sWo1[u0 + 1];
                z0b += v2 * sWo0[u0] + v3 * sWo0[u0 + 1];
                z1b += v2 * sWo1[u0] + v3 * sWo1[u0 + 1];

                Pout[(2 * f) * 32]     = packh2(v0, v1);
                Pout[(2 * f + 1) * 32] = packh2(v2, v3);
            }

            // z quad-reduce + store (reducer consumers)
            z0a += __shfl_xor_sync(0xffffffffu, z0a, 1);
            z0a += __shfl_xor_sync(0xffffffffu, z0a, 2);
            z1a += __shfl_xor_sync(0xffffffffu, z1a, 1);
            z1a += __shfl_xor_sync(0xffffffffu, z1a, 2);
            z0b += __shfl_xor_sync(0xffffffffu, z0b, 1);
            z0b += __shfl_xor_sync(0xffffffffu, z0b, 2);
            z1b += __shfl_xor_sync(0xffffffffu, z1b, 1);
            z1b += __shfl_xor_sync(0xffffffffu, z1b, 2);
            if (tg == 0) {
                float2* zp = g_zpart + (((t & (ZDEPTH - 1)) * NTn + n) * 4 + w) * B_;
                int bA = 16 * m + q;
                zp[bA]     = make_float2(z0a, z1a);
                zp[bA + 8] = make_float2(z0b, z1b);
            }

            bar_sync(1, 128);                    // all fresh stores done
            if (tid == 0) st_release(&g_flags[bx], t);
        } else {
            // ======== CV GROUP (warps 4-7, tid 128..255) ========
            if (oldcv) {
                cp_wait<0>();                    // own prefetch (end of t-1) landed
                bar_sync(2, 128);                // whole cv group staged
                float acc[2][4];
#pragma unroll
                for (int f = 0; f < 2; ++f)
                    acc[f][0] = acc[f][1] = acc[f][2] = acc[f][3] = 0.f;
                gemm_ldsm_n<32>(sCV_s + aOff, bOff + 1024, acc);
                float4* pp = (float4*)(sP + (wc * 32 + lane) * 8);
                pp[0] = make_float4(acc[0][0], acc[0][1], acc[0][2], acc[0][3]);
                pp[1] = make_float4(acc[1][0], acc[1][1], acc[1][2], acc[1][3]);
            }
            bar_sync(2, 128);                    // cv group done reading sCV

            // prefetch next step's old-cv tile into sCV
            if (t < T_STEPS) {
                int r2 = t >> 4, p2 = t & 15;
                if (p2 >= 1 && r2 >= 1) {
                    int c2 = (r2 & 1) ? (15 - p2) : p2;
                    const unsigned* src = pslab((r2 - 1) & 1, c2) + (m << 12);
                    int tl = tid - 128;
#pragma unroll
                    for (int i = 0; i < 8; ++i)
                        cp_async16(sCV_s + tl * 16 + i * 2048, src + tl * 4 + i * 512);
                }
                cp_commit();
            }

            __syncthreads();                     // join (partials visible to fresh)
        }
    }
}

extern "C" void kernel_launch(void* const* d_in, const int* in_sizes, int n_in,
                              void* d_out, int out_size)
{
    (void)in_sizes; (void)n_in; (void)out_size;
    const int*   x    = (const int*)  d_in[0];
    const float* Wih  = (const float*)d_in[1];
    const float* Wiv  = (const float*)d_in[2];
    const float* Wch  = (const float*)d_in[3];
    const float* bch  = (const float*)d_in[4];
    const float* Wcv  = (const float*)d_in[5];
    const float* Wout = (const float*)d_in[6];
    const float* bout = (const float*)d_in[7];
    float* out = (float*)d_out;

    cudaFuncSetAttribute(rnn2d_main_kernel,
                         cudaFuncAttributeMaxDynamicSharedMemorySize, SM_TOTAL);

    rnn2d_init_kernel<<<1, 128>>>();
    rnn2d_main_kernel<<<NCOMP + NRED, THREADS, SM_TOTAL>>>(
        x, Wih, Wiv, Wch, bch, Wcv, Wout, bout, out);
}